// round 12
// baseline (speedup 1.0000x reference)
#include <cuda_runtime.h>
#include <cuda_bf16.h>

#define BB 64
#define LL 200
#define DD 128
#define MM 50
#define NQ 10000
#define TOK 16          // tokens per precompute block
#define TOK2 16         // tokens per final block

// ---- device scratch ----
__device__ float  g_w[BB * LL * MM];       // softmax weights  [B,L,50]
__device__ float  g_e[BB * LL * DD];       // sigmoid gate     [B,L,128]
__device__ float  g_a[BB * LL * DD];       // tanh add         [B,L,128]
__device__ float  g_rp[BB * LL * DD];      // fully-reduced read [B,L,128]
__device__ float  g_fk[BB * LL * 2 * DD];  // k-half f partials [tok][ih][o]
__device__ float4 g_We4[32 * DD];          // eW packed: [j4][d]
__device__ float4 g_Wa4[32 * DD];          // aW packed
__device__ float4 g_Mk4[32 * 64];          // Mk packed: [j4][m(pad64)]
__device__ float4 g_Wf4[64 * DD];          // fW packed: [j4 0..63][d]; j4>=32 = k half

// ---- packed f32x2 FMA (Blackwell) ----
__device__ __forceinline__ float2 ffma2(float2 a, float2 b, float2 c) {
    float2 d;
    asm("fma.rn.f32x2 %0, %1, %2, %3;"
        : "=l"(*reinterpret_cast<unsigned long long*>(&d))
        : "l"(*reinterpret_cast<unsigned long long*>(&a)),
          "l"(*reinterpret_cast<unsigned long long*>(&b)),
          "l"(*reinterpret_cast<unsigned long long*>(&c)));
    return d;
}
__device__ __forceinline__ float2 f2(float x, float y) { return make_float2(x, y); }

// ============================================================================
// Kernel T: weight transposes into packed-j4 layouts
// ============================================================================
__global__ void transpose_kernel(const float* __restrict__ eW, const float* __restrict__ aW,
                                 const float* __restrict__ Mk, const float* __restrict__ fW)
{
    int i = blockIdx.x * 256 + threadIdx.x;
    if (i < 4096) {                       // e_W,a_W: [128 d][32 j4]
        int d = i >> 5, j4 = i & 31;
        g_We4[j4 * 128 + d] = ((const float4*)eW)[d * 32 + j4];
        g_Wa4[j4 * 128 + d] = ((const float4*)aW)[d * 32 + j4];
    } else if (i < 6144) {                // Mk: [50 m][32 j4] -> [32 j4][64 m]
        int t = i - 4096;
        int m = t >> 5, j4 = t & 31;
        g_Mk4[j4 * 64 + m] = (m < MM) ? ((const float4*)Mk)[m * 32 + j4]
                                      : make_float4(0.f, 0.f, 0.f, 0.f);
    } else if (i < 14336) {               // f_W: [128 d][64 j4] -> [64 j4][128 d]
        int t = i - 6144;
        int d = t >> 6, j4 = t & 63;
        g_Wf4[j4 * 128 + d] = ((const float4*)fW)[d * 64 + j4];
    }
}

// ============================================================================
// Kernel A: 16 tokens/block, 256 threads, 800 blocks.
// ============================================================================
__global__ __launch_bounds__(256) void precompute_kernel(
    const int* __restrict__ q, const int* __restrict__ r,
    const float* __restrict__ k_emb, const float* __restrict__ v_emb,
    const float* __restrict__ e_b, const float* __restrict__ a_b)
{
    __shared__ float k_s[TOK * DD];
    __shared__ float v_s[TOK * DD];
    __shared__ float lg_s[TOK * 52];
    __shared__ int qs[TOK], xs[TOK];

    int tid = threadIdx.x;
    int bl0 = blockIdx.x * TOK;

    if (tid < TOK) {
        int qi = q[bl0 + tid];
        qs[tid] = qi;
        xs[tid] = qi + NQ * r[bl0 + tid];
    }
    __syncthreads();

    float4* k4 = (float4*)k_s;
    float4* v4 = (float4*)v_s;
    const float4* ke4 = (const float4*)k_emb;
    const float4* ve4 = (const float4*)v_emb;
    for (int i = tid; i < TOK * 32; i += 256) {
        int tok = i >> 5, j = i & 31;
        k4[i] = ke4[qs[tok] * 32 + j];
        v4[i] = ve4[xs[tok] * 32 + j];
    }
    __syncthreads();

    // ---- logits: threads = (m 0..63) x (4 token-groups of 4), f32x2 FMA ----
    {
        int m = tid & 63, tg = tid >> 6;
        float2 a0 = f2(0, 0), a1 = f2(0, 0), a2 = f2(0, 0), a3 = f2(0, 0);
        #pragma unroll 4
        for (int j4 = 0; j4 < 32; j4++) {
            float4 mk = g_Mk4[j4 * 64 + m];
            float2 mlo = f2(mk.x, mk.y), mhi = f2(mk.z, mk.w);
            float4 c0 = k4[(tg * 4 + 0) * 32 + j4];
            float4 c1 = k4[(tg * 4 + 1) * 32 + j4];
            float4 c2 = k4[(tg * 4 + 2) * 32 + j4];
            float4 c3 = k4[(tg * 4 + 3) * 32 + j4];
            a0 = ffma2(mlo, f2(c0.x, c0.y), a0); a0 = ffma2(mhi, f2(c0.z, c0.w), a0);
            a1 = ffma2(mlo, f2(c1.x, c1.y), a1); a1 = ffma2(mhi, f2(c1.z, c1.w), a1);
            a2 = ffma2(mlo, f2(c2.x, c2.y), a2); a2 = ffma2(mhi, f2(c2.z, c2.w), a2);
            a3 = ffma2(mlo, f2(c3.x, c3.y), a3); a3 = ffma2(mhi, f2(c3.z, c3.w), a3);
        }
        if (m < MM) {
            lg_s[(tg * 4 + 0) * 52 + m] = a0.x + a0.y;
            lg_s[(tg * 4 + 1) * 52 + m] = a1.x + a1.y;
            lg_s[(tg * 4 + 2) * 52 + m] = a2.x + a2.y;
            lg_s[(tg * 4 + 3) * 52 + m] = a3.x + a3.y;
        }
    }
    __syncthreads();

    // ---- softmax: 8 warps x 2 tokens ----
    {
        int wid = tid >> 5, lane = tid & 31;
        for (int tok = wid * 2; tok < wid * 2 + 2; tok++) {
            float v0 = lg_s[tok * 52 + lane];
            float v1 = (lane < MM - 32) ? lg_s[tok * 52 + 32 + lane] : -1e30f;
            float mx = fmaxf(v0, v1);
            #pragma unroll
            for (int o = 16; o; o >>= 1) mx = fmaxf(mx, __shfl_xor_sync(0xFFFFFFFFu, mx, o));
            float e0 = expf(v0 - mx);
            float e1 = (lane < MM - 32) ? expf(v1 - mx) : 0.f;
            float s = e0 + e1;
            #pragma unroll
            for (int o = 16; o; o >>= 1) s += __shfl_xor_sync(0xFFFFFFFFu, s, o);
            float inv = 1.f / s;
            int g = bl0 + tok;
            g_w[g * MM + lane] = e0 * inv;
            if (lane < MM - 32) g_w[g * MM + 32 + lane] = e1 * inv;
        }
    }

    // ---- e/a GEMV: threads = (d 0..127) x (2 token-groups of 8), f32x2 ----
    {
        int d = tid & 127, tg = tid >> 7;
        float2 ae[8], aa[8];
        #pragma unroll
        for (int t = 0; t < 8; t++) { ae[t] = f2(0, 0); aa[t] = f2(0, 0); }
        #pragma unroll 4
        for (int j4 = 0; j4 < 32; j4++) {
            float4 we = g_We4[j4 * 128 + d];
            float4 wa = g_Wa4[j4 * 128 + d];
            float2 welo = f2(we.x, we.y), wehi = f2(we.z, we.w);
            float2 walo = f2(wa.x, wa.y), wahi = f2(wa.z, wa.w);
            #pragma unroll
            for (int t = 0; t < 8; t++) {
                float4 v = v4[(tg * 8 + t) * 32 + j4];
                float2 vlo = f2(v.x, v.y), vhi = f2(v.z, v.w);
                ae[t] = ffma2(welo, vlo, ae[t]); ae[t] = ffma2(wehi, vhi, ae[t]);
                aa[t] = ffma2(walo, vlo, aa[t]); aa[t] = ffma2(wahi, vhi, aa[t]);
            }
        }
        float eb = e_b[d], ab = a_b[d];
        #pragma unroll
        for (int t = 0; t < 8; t++) {
            int g = bl0 + tg * 8 + t;
            g_e[g * DD + d] = 1.f / (1.f + expf(-(ae[t].x + ae[t].y + eb)));
            g_a[g * DD + d] = tanhf(aa[t].x + aa[t].y + ab);
        }
    }
}

// ============================================================================
// Kernel B: sequential scan + interleaved k-half f-GEMV.
// grid = 64 b x 2 d-halves; 160 threads = (10 m-groups of 5) x (16 f4 lanes).
// DRAM-bound Mv stream leaves issue slots idle; threads 0-127 use them to
// compute the scan-independent k-half of f = [rp|k] fW^T for token t each
// step (no extra barriers - kbuf parity hazards covered by the existing
// per-step __syncthreads), threads 128-159 prefetch k[t+1].
// ============================================================================
__global__ void scan_kernel(const int* __restrict__ q,
                            const float* __restrict__ k_emb,
                            const float* __restrict__ Mv0,
                            float* __restrict__ mv_out, int write_mv)
{
    __shared__ float4 sm_rp[2][10][16];
    __shared__ float4 kbuf[2][32];
    __shared__ int    qs_s[LL];

    int b   = blockIdx.x >> 1;
    int dh  = blockIdx.x & 1;
    int tid = threadIdx.x;
    int l16 = tid & 15;
    int mg  = tid >> 4;          // 0..9
    int m0  = mg * 5;
    int d   = dh * 64 + l16 * 4;

    const float4* ke4 = (const float4*)k_emb;
    for (int i = tid; i < LL; i += 160) qs_s[i] = q[b * LL + i];
    __syncthreads();
    if (tid >= 128) kbuf[0][tid - 128] = ke4[qs_s[0] * 32 + (tid - 128)];

    const float4* Mv04 = (const float4*)Mv0;
    float2 Slo[5], Shi[5];
    #pragma unroll
    for (int i = 0; i < 5; i++) {
        float4 s = Mv04[((m0 + i) * DD + d) >> 2];
        Slo[i] = f2(s.x, s.y);
        Shi[i] = f2(s.z, s.w);
    }

    float4* out4 = (float4*)mv_out;
    long base201 = (long)b * 201 * (MM * DD);
    if (write_mv) {
        #pragma unroll
        for (int i = 0; i < 5; i++)
            __stcs(&out4[(base201 + (m0 + i) * DD + d) >> 2],
                   make_float4(Slo[i].x, Slo[i].y, Shi[i].x, Shi[i].y));
    }

    const float4* e4p = (const float4*)g_e;
    const float4* a4p = (const float4*)g_a;
    int  wbase  = (b * LL) * MM + m0;
    int  eabase = ((b * LL) * DD + d) >> 2;
    long obase  = base201 + MM * DD;
    int  rpbase = (b * LL) * DD + dh * 64;

    // k-half GEMV role constants (threads 0-127)
    int o64 = tid & 63, ih = (tid >> 6) & 1;
    int fko = dh * 64 + o64;
    int fkbase = (b * LL) * 2 * DD;

    // prefetch t = 0
    float wv[5];
    #pragma unroll
    for (int i = 0; i < 5; i++) wv[i] = g_w[wbase + i];
    float4 ecur = e4p[eabase];
    float4 acur = a4p[eabase];

    for (int t = 0; t < LL; t++) {
        // prefetch t+1 (w/e/a)
        int tn = (t + 1 < LL) ? t + 1 : t;
        float wn[5];
        #pragma unroll
        for (int i = 0; i < 5; i++) wn[i] = g_w[wbase + tn * MM + i];
        float4 en = e4p[eabase + tn * 32];
        float4 an = a4p[eabase + tn * 32];

        float2 nelo = f2(-ecur.x, -ecur.y), nehi = f2(-ecur.z, -ecur.w);
        float2 alo  = f2(acur.x, acur.y),   ahi  = f2(acur.z, acur.w);
        float2 rlo  = f2(0.f, 0.f),         rhi  = f2(0.f, 0.f);

        long ob = obase + (long)t * (MM * DD);
        #pragma unroll
        for (int i = 0; i < 5; i++) {
            float2 w2 = f2(wv[i], wv[i]);
            rlo = ffma2(w2, Slo[i], rlo);
            rhi = ffma2(w2, Shi[i], rhi);
            float2 tlo = ffma2(nelo, Slo[i], alo);
            float2 thi = ffma2(nehi, Shi[i], ahi);
            Slo[i] = ffma2(w2, tlo, Slo[i]);
            Shi[i] = ffma2(w2, thi, Shi[i]);
            if (write_mv)
                __stcs(&out4[(ob + (m0 + i) * DD + d) >> 2],
                       make_float4(Slo[i].x, Slo[i].y, Shi[i].x, Shi[i].y));
        }

        sm_rp[t & 1][mg][l16] = make_float4(rlo.x, rlo.y, rhi.x, rhi.y);
        __syncthreads();
        // ---- late part: reducers + k-half GEMV + k prefetch ----
        if (tid < 64) {
            const float* sp = (const float*)sm_rp[t & 1];
            float s = 0.f;
            #pragma unroll
            for (int g = 0; g < 10; g++) s += sp[g * 64 + tid];
            g_rp[rpbase + t * DD + tid] = s;
        }
        if (tid < 128) {
            // k-half of f GEMV for token t: output fko, input half ih.
            float2 acc = f2(0.f, 0.f);
            #pragma unroll
            for (int j = 0; j < 16; j++) {
                float4 w = g_Wf4[(32 + ih * 16 + j) * 128 + fko];
                float4 c = kbuf[t & 1][ih * 16 + j];
                acc = ffma2(f2(w.x, w.y), f2(c.x, c.y), acc);
                acc = ffma2(f2(w.z, w.w), f2(c.z, c.w), acc);
            }
            g_fk[fkbase + (t * 2 + ih) * DD + fko] = acc.x + acc.y;
        } else if (t + 1 < LL) {
            kbuf[(t + 1) & 1][tid - 128] = ke4[qs_s[t + 1] * 32 + (tid - 128)];
        }
        // sm_rp[t&1] next rewritten at t+2 (after the t+1 barrier) -> safe.
        // kbuf[(t+1)&1] write vs its last read (GEMV at t-1) is separated by
        // this step's barrier -> safe.

        #pragma unroll
        for (int i = 0; i < 5; i++) wv[i] = wn[i];
        ecur = en;
        acur = an;
    }
}

// ============================================================================
// Kernel C: 16 tokens/block, 256 threads, 800 blocks.
// f = tanh(rp-half GEMV + precomputed k-half partials + fb); p = sigma(...)
// ============================================================================
__global__ __launch_bounds__(256) void final_kernel(
    const float* __restrict__ f_b, const float* __restrict__ p_W,
    const float* __restrict__ p_b, float* __restrict__ p_out)
{
    __shared__ float cat_s[TOK2 * 256];   // first 8KB = rp stage; reused for f

    int tid = threadIdx.x;
    int bl0 = blockIdx.x * TOK2;

    float4* cat4 = (float4*)cat_s;
    const float4* rp4 = (const float4*)g_rp;
    for (int i = tid; i < TOK2 * 32; i += 256) {
        int tok = i >> 5, jj = i & 31;
        cat4[tok * 32 + jj] = rp4[(bl0 + tok) * 32 + jj];
    }
    __syncthreads();

    // rp-half GEMV: threads = (d 0..127) x (2 token-groups of 8), f32x2
    int d = tid & 127, tg = tid >> 7;
    float2 acc[8];
    float fk[8];
    #pragma unroll
    for (int t = 0; t < 8; t++) {
        acc[t] = f2(0, 0);
        int gtok = bl0 + tg * 8 + t;
        fk[t] = g_fk[(gtok * 2) * DD + d] + g_fk[(gtok * 2 + 1) * DD + d];
    }
    #pragma unroll 8
    for (int j4 = 0; j4 < 32; j4++) {
        float4 w = g_Wf4[j4 * 128 + d];
        float2 wlo = f2(w.x, w.y), whi = f2(w.z, w.w);
        #pragma unroll
        for (int t = 0; t < 8; t++) {
            float4 c = cat4[(tg * 8 + t) * 32 + j4];
            acc[t] = ffma2(wlo, f2(c.x, c.y), acc[t]);
            acc[t] = ffma2(whi, f2(c.z, c.w), acc[t]);
        }
    }
    float fb = f_b[d], pw = p_W[d];
    __syncthreads();   // all reads of cat_s done; reuse for f values
    #pragma unroll
    for (int t = 0; t < 8; t++)
        cat_s[(tg * 8 + t) * 128 + d] =
            tanhf(acc[t].x + acc[t].y + fk[t] + fb) * pw;
    __syncthreads();

    // reduce over d: 8 warps x 2 tokens
    {
        int wid = tid >> 5, lane = tid & 31;
        float pb = p_b[0];
        for (int tok = wid * 2; tok < wid * 2 + 2; tok++) {
            float s = cat_s[tok * 128 + lane] + cat_s[tok * 128 + lane + 32]
                    + cat_s[tok * 128 + lane + 64] + cat_s[tok * 128 + lane + 96];
            #pragma unroll
            for (int o = 16; o; o >>= 1) s += __shfl_xor_sync(0xFFFFFFFFu, s, o);
            if (lane == 0) p_out[bl0 + tok] = 1.f / (1.f + expf(-(s + pb)));
        }
    }
}

// ============================================================================
extern "C" void kernel_launch(void* const* d_in, const int* in_sizes, int n_in,
                              void* d_out, int out_size)
{
    const int*   q     = (const int*)  d_in[0];
    const int*   r     = (const int*)  d_in[1];
    const float* k_emb = (const float*)d_in[2];
    const float* v_emb = (const float*)d_in[3];
    const float* Mk    = (const float*)d_in[4];
    const float* Mv0   = (const float*)d_in[5];
    const float* f_W   = (const float*)d_in[6];
    const float* f_b   = (const float*)d_in[7];
    const float* p_W   = (const float*)d_in[8];
    const float* p_b   = (const float*)d_in[9];
    const float* e_W   = (const float*)d_in[10];
    const float* e_b   = (const float*)d_in[11];
    const float* a_W   = (const float*)d_in[12];
    const float* a_b   = (const float*)d_in[13];

    float* out = (float*)d_out;
    const int  P_CNT  = BB * LL;                     // 12800
    const long MV_CNT = (long)BB * 201 * MM * DD;    // 82,329,600

    float* p_out  = out;
    float* mv_out = out;
    int write_mv  = 0;
    if ((long)out_size >= (long)P_CNT + MV_CNT) {
        mv_out = out + P_CNT;
        write_mv = 1;
    }

    transpose_kernel<<<56, 256>>>(e_W, a_W, Mk, f_W);
    precompute_kernel<<<BB * LL / TOK, 256>>>(q, r, k_emb, v_emb, e_b, a_b);
    scan_kernel<<<BB * 2, 160>>>(q, k_emb, Mv0, mv_out, write_mv);
    final_kernel<<<BB * LL / TOK2, 256>>>(f_b, p_W, p_b, p_out);
}

// round 13
// speedup vs baseline: 1.1924x; 1.1924x over previous
#include <cuda_runtime.h>
#include <cuda_bf16.h>

#define BB 64
#define LL 200
#define DD 128
#define MM 50
#define NQ 10000
#define TOK 16          // tokens per precompute block
#define TOK2 16         // tokens per final block

// ---- device scratch ----
__device__ float  g_w[BB * LL * MM];       // softmax weights  [B,L,50]
__device__ float  g_e[BB * LL * DD];       // sigmoid gate     [B,L,128]
__device__ float  g_a[BB * LL * DD];       // tanh add         [B,L,128]
__device__ float  g_rp[BB * LL * DD];      // fully-reduced read [B,L,128]
__device__ float  g_fk[BB * LL * DD];      // k-half f partial [tok][o]
__device__ float4 g_We4[32 * DD];          // eW packed: [j4][d]
__device__ float4 g_Wa4[32 * DD];          // aW packed
__device__ float4 g_Mk4[32 * 64];          // Mk packed: [j4][m(pad64)]
__device__ float4 g_Wf4[64 * DD];          // fW packed: [j4 0..63][d]; j4>=32 = k half

// ---- packed f32x2 FMA (Blackwell) ----
__device__ __forceinline__ float2 ffma2(float2 a, float2 b, float2 c) {
    float2 d;
    asm("fma.rn.f32x2 %0, %1, %2, %3;"
        : "=l"(*reinterpret_cast<unsigned long long*>(&d))
        : "l"(*reinterpret_cast<unsigned long long*>(&a)),
          "l"(*reinterpret_cast<unsigned long long*>(&b)),
          "l"(*reinterpret_cast<unsigned long long*>(&c)));
    return d;
}
__device__ __forceinline__ float2 f2(float x, float y) { return make_float2(x, y); }

// ============================================================================
// Kernel T: weight transposes into packed-j4 layouts
// ============================================================================
__global__ void transpose_kernel(const float* __restrict__ eW, const float* __restrict__ aW,
                                 const float* __restrict__ Mk, const float* __restrict__ fW)
{
    int i = blockIdx.x * 256 + threadIdx.x;
    if (i < 4096) {                       // e_W,a_W: [128 d][32 j4]
        int d = i >> 5, j4 = i & 31;
        g_We4[j4 * 128 + d] = ((const float4*)eW)[d * 32 + j4];
        g_Wa4[j4 * 128 + d] = ((const float4*)aW)[d * 32 + j4];
    } else if (i < 6144) {                // Mk: [50 m][32 j4] -> [32 j4][64 m]
        int t = i - 4096;
        int m = t >> 5, j4 = t & 31;
        g_Mk4[j4 * 64 + m] = (m < MM) ? ((const float4*)Mk)[m * 32 + j4]
                                      : make_float4(0.f, 0.f, 0.f, 0.f);
    } else if (i < 14336) {               // f_W: [128 d][64 j4] -> [64 j4][128 d]
        int t = i - 6144;
        int d = t >> 6, j4 = t & 63;
        g_Wf4[j4 * 128 + d] = ((const float4*)fW)[d * 64 + j4];
    }
}

// ============================================================================
// Kernel A: 16 tokens/block, 256 threads, 800 blocks.
// w = softmax(k Mk^T); e = sigma(v eW^T); a = tanh(v aW^T);
// fk = k . fW_khalf^T   (scan-independent half of the output gate GEMV)
// ============================================================================
__global__ __launch_bounds__(256) void precompute_kernel(
    const int* __restrict__ q, const int* __restrict__ r,
    const float* __restrict__ k_emb, const float* __restrict__ v_emb,
    const float* __restrict__ e_b, const float* __restrict__ a_b)
{
    __shared__ float k_s[TOK * DD];
    __shared__ float v_s[TOK * DD];
    __shared__ float lg_s[TOK * 52];
    __shared__ int qs[TOK], xs[TOK];

    int tid = threadIdx.x;
    int bl0 = blockIdx.x * TOK;

    if (tid < TOK) {
        int qi = q[bl0 + tid];
        qs[tid] = qi;
        xs[tid] = qi + NQ * r[bl0 + tid];
    }
    __syncthreads();

    float4* k4 = (float4*)k_s;
    float4* v4 = (float4*)v_s;
    const float4* ke4 = (const float4*)k_emb;
    const float4* ve4 = (const float4*)v_emb;
    for (int i = tid; i < TOK * 32; i += 256) {
        int tok = i >> 5, j = i & 31;
        k4[i] = ke4[qs[tok] * 32 + j];
        v4[i] = ve4[xs[tok] * 32 + j];
    }
    __syncthreads();

    // ---- logits: threads = (m 0..63) x (4 token-groups of 4), f32x2 FMA ----
    {
        int m = tid & 63, tg = tid >> 6;
        float2 a0 = f2(0, 0), a1 = f2(0, 0), a2 = f2(0, 0), a3 = f2(0, 0);
        #pragma unroll 4
        for (int j4 = 0; j4 < 32; j4++) {
            float4 mk = g_Mk4[j4 * 64 + m];
            float2 mlo = f2(mk.x, mk.y), mhi = f2(mk.z, mk.w);
            float4 c0 = k4[(tg * 4 + 0) * 32 + j4];
            float4 c1 = k4[(tg * 4 + 1) * 32 + j4];
            float4 c2 = k4[(tg * 4 + 2) * 32 + j4];
            float4 c3 = k4[(tg * 4 + 3) * 32 + j4];
            a0 = ffma2(mlo, f2(c0.x, c0.y), a0); a0 = ffma2(mhi, f2(c0.z, c0.w), a0);
            a1 = ffma2(mlo, f2(c1.x, c1.y), a1); a1 = ffma2(mhi, f2(c1.z, c1.w), a1);
            a2 = ffma2(mlo, f2(c2.x, c2.y), a2); a2 = ffma2(mhi, f2(c2.z, c2.w), a2);
            a3 = ffma2(mlo, f2(c3.x, c3.y), a3); a3 = ffma2(mhi, f2(c3.z, c3.w), a3);
        }
        if (m < MM) {
            lg_s[(tg * 4 + 0) * 52 + m] = a0.x + a0.y;
            lg_s[(tg * 4 + 1) * 52 + m] = a1.x + a1.y;
            lg_s[(tg * 4 + 2) * 52 + m] = a2.x + a2.y;
            lg_s[(tg * 4 + 3) * 52 + m] = a3.x + a3.y;
        }
    }
    __syncthreads();

    // ---- softmax: 8 warps x 2 tokens ----
    {
        int wid = tid >> 5, lane = tid & 31;
        for (int tok = wid * 2; tok < wid * 2 + 2; tok++) {
            float v0 = lg_s[tok * 52 + lane];
            float v1 = (lane < MM - 32) ? lg_s[tok * 52 + 32 + lane] : -1e30f;
            float mx = fmaxf(v0, v1);
            #pragma unroll
            for (int o = 16; o; o >>= 1) mx = fmaxf(mx, __shfl_xor_sync(0xFFFFFFFFu, mx, o));
            float e0 = expf(v0 - mx);
            float e1 = (lane < MM - 32) ? expf(v1 - mx) : 0.f;
            float s = e0 + e1;
            #pragma unroll
            for (int o = 16; o; o >>= 1) s += __shfl_xor_sync(0xFFFFFFFFu, s, o);
            float inv = 1.f / s;
            int g = bl0 + tok;
            g_w[g * MM + lane] = e0 * inv;
            if (lane < MM - 32) g_w[g * MM + 32 + lane] = e1 * inv;
        }
    }

    // ---- e/a GEMV: threads = (d 0..127) x (2 token-groups of 8), f32x2 ----
    int d = tid & 127, tg = tid >> 7;
    {
        float2 ae[8], aa[8];
        #pragma unroll
        for (int t = 0; t < 8; t++) { ae[t] = f2(0, 0); aa[t] = f2(0, 0); }
        #pragma unroll 4
        for (int j4 = 0; j4 < 32; j4++) {
            float4 we = g_We4[j4 * 128 + d];
            float4 wa = g_Wa4[j4 * 128 + d];
            float2 welo = f2(we.x, we.y), wehi = f2(we.z, we.w);
            float2 walo = f2(wa.x, wa.y), wahi = f2(wa.z, wa.w);
            #pragma unroll
            for (int t = 0; t < 8; t++) {
                float4 v = v4[(tg * 8 + t) * 32 + j4];
                float2 vlo = f2(v.x, v.y), vhi = f2(v.z, v.w);
                ae[t] = ffma2(welo, vlo, ae[t]); ae[t] = ffma2(wehi, vhi, ae[t]);
                aa[t] = ffma2(walo, vlo, aa[t]); aa[t] = ffma2(wahi, vhi, aa[t]);
            }
        }
        float eb = e_b[d], ab = a_b[d];
        #pragma unroll
        for (int t = 0; t < 8; t++) {
            int g = bl0 + tg * 8 + t;
            g_e[g * DD + d] = 1.f / (1.f + expf(-(ae[t].x + ae[t].y + eb)));
            g_a[g * DD + d] = tanhf(aa[t].x + aa[t].y + ab);
        }
    }

    // ---- fk GEMV (k-half of f): same layout, inputs = k_s, weights j4>=32 ----
    {
        float2 fk[8];
        #pragma unroll
        for (int t = 0; t < 8; t++) fk[t] = f2(0, 0);
        #pragma unroll 4
        for (int j4 = 0; j4 < 32; j4++) {
            float4 w = g_Wf4[(32 + j4) * 128 + d];
            float2 wlo = f2(w.x, w.y), whi = f2(w.z, w.w);
            #pragma unroll
            for (int t = 0; t < 8; t++) {
                float4 c = k4[(tg * 8 + t) * 32 + j4];
                fk[t] = ffma2(wlo, f2(c.x, c.y), fk[t]);
                fk[t] = ffma2(whi, f2(c.z, c.w), fk[t]);
            }
        }
        #pragma unroll
        for (int t = 0; t < 8; t++)
            g_fk[(bl0 + tg * 8 + t) * DD + d] = fk[t].x + fk[t].y;
    }
}

// ============================================================================
// Kernel B: sequential scan (R11 form, untouched). grid = 64 b x 2 d-halves;
// 160 threads = (10 m-groups of 5) x (16 float4-d lanes). Prefetched loads,
// f32x2 math, in-block rp reduction (parity smem, 1 sync/step), __stcs Mv.
// ============================================================================
__global__ void scan_kernel(const float* __restrict__ Mv0,
                            float* __restrict__ mv_out, int write_mv)
{
    __shared__ float4 sm_rp[2][10][16];

    int b   = blockIdx.x >> 1;
    int dh  = blockIdx.x & 1;
    int tid = threadIdx.x;
    int l16 = tid & 15;
    int mg  = tid >> 4;          // 0..9
    int m0  = mg * 5;
    int d   = dh * 64 + l16 * 4;

    const float4* Mv04 = (const float4*)Mv0;
    float2 Slo[5], Shi[5];
    #pragma unroll
    for (int i = 0; i < 5; i++) {
        float4 s = Mv04[((m0 + i) * DD + d) >> 2];
        Slo[i] = f2(s.x, s.y);
        Shi[i] = f2(s.z, s.w);
    }

    float4* out4 = (float4*)mv_out;
    long base201 = (long)b * 201 * (MM * DD);
    if (write_mv) {
        #pragma unroll
        for (int i = 0; i < 5; i++)
            __stcs(&out4[(base201 + (m0 + i) * DD + d) >> 2],
                   make_float4(Slo[i].x, Slo[i].y, Shi[i].x, Shi[i].y));
    }

    const float4* e4p = (const float4*)g_e;
    const float4* a4p = (const float4*)g_a;
    int  wbase  = (b * LL) * MM + m0;
    int  eabase = ((b * LL) * DD + d) >> 2;
    long obase  = base201 + MM * DD;
    int  rpbase = (b * LL) * DD + dh * 64;

    // prefetch t = 0
    float wv[5];
    #pragma unroll
    for (int i = 0; i < 5; i++) wv[i] = g_w[wbase + i];
    float4 ecur = e4p[eabase];
    float4 acur = a4p[eabase];

    for (int t = 0; t < LL; t++) {
        // prefetch t+1
        int tn = (t + 1 < LL) ? t + 1 : t;
        float wn[5];
        #pragma unroll
        for (int i = 0; i < 5; i++) wn[i] = g_w[wbase + tn * MM + i];
        float4 en = e4p[eabase + tn * 32];
        float4 an = a4p[eabase + tn * 32];

        float2 nelo = f2(-ecur.x, -ecur.y), nehi = f2(-ecur.z, -ecur.w);
        float2 alo  = f2(acur.x, acur.y),   ahi  = f2(acur.z, acur.w);
        float2 rlo  = f2(0.f, 0.f),         rhi  = f2(0.f, 0.f);

        long ob = obase + (long)t * (MM * DD);
        #pragma unroll
        for (int i = 0; i < 5; i++) {
            float2 w2 = f2(wv[i], wv[i]);
            rlo = ffma2(w2, Slo[i], rlo);
            rhi = ffma2(w2, Shi[i], rhi);
            float2 tlo = ffma2(nelo, Slo[i], alo);
            float2 thi = ffma2(nehi, Shi[i], ahi);
            Slo[i] = ffma2(w2, tlo, Slo[i]);
            Shi[i] = ffma2(w2, thi, Shi[i]);
            if (write_mv)
                __stcs(&out4[(ob + (m0 + i) * DD + d) >> 2],
                       make_float4(Slo[i].x, Slo[i].y, Shi[i].x, Shi[i].y));
        }

        sm_rp[t & 1][mg][l16] = make_float4(rlo.x, rlo.y, rhi.x, rhi.y);
        __syncthreads();
        if (tid < 64) {
            const float* sp = (const float*)sm_rp[t & 1];
            float s = 0.f;
            #pragma unroll
            for (int g = 0; g < 10; g++) s += sp[g * 64 + tid];
            g_rp[rpbase + t * DD + tid] = s;
        }
        // Single barrier per step is safe: buffer t&1 is read between the
        // barriers at t and t+1, and next rewritten only at t+2, which is
        // after the t+1 barrier that the reducer threads also join.

        #pragma unroll
        for (int i = 0; i < 5; i++) wv[i] = wn[i];
        ecur = en;
        acur = an;
    }
}

// ============================================================================
// Kernel C: 16 tokens/block, 256 threads, 800 blocks.
// f = tanh(rp-half GEMV + precomputed fk + fb); p = sigma(f . pW + pb)
// ============================================================================
__global__ __launch_bounds__(256) void final_kernel(
    const float* __restrict__ f_b, const float* __restrict__ p_W,
    const float* __restrict__ p_b, float* __restrict__ p_out)
{
    __shared__ float cat_s[TOK2 * 256];   // first 8KB = rp stage; reused for f

    int tid = threadIdx.x;
    int bl0 = blockIdx.x * TOK2;

    float4* cat4 = (float4*)cat_s;
    const float4* rp4 = (const float4*)g_rp;
    for (int i = tid; i < TOK2 * 32; i += 256) {
        int tok = i >> 5, jj = i & 31;
        cat4[tok * 32 + jj] = rp4[(bl0 + tok) * 32 + jj];
    }
    __syncthreads();

    // rp-half GEMV: threads = (d 0..127) x (2 token-groups of 8), f32x2
    int d = tid & 127, tg = tid >> 7;
    float2 acc[8];
    float fk[8];
    #pragma unroll
    for (int t = 0; t < 8; t++) {
        acc[t] = f2(0, 0);
        fk[t] = g_fk[(bl0 + tg * 8 + t) * DD + d];
    }
    #pragma unroll 8
    for (int j4 = 0; j4 < 32; j4++) {
        float4 w = g_Wf4[j4 * 128 + d];
        float2 wlo = f2(w.x, w.y), whi = f2(w.z, w.w);
        #pragma unroll
        for (int t = 0; t < 8; t++) {
            float4 c = cat4[(tg * 8 + t) * 32 + j4];
            acc[t] = ffma2(wlo, f2(c.x, c.y), acc[t]);
            acc[t] = ffma2(whi, f2(c.z, c.w), acc[t]);
        }
    }
    float fb = f_b[d], pw = p_W[d];
    __syncthreads();   // all reads of cat_s done; reuse for f values
    #pragma unroll
    for (int t = 0; t < 8; t++)
        cat_s[(tg * 8 + t) * 128 + d] =
            tanhf(acc[t].x + acc[t].y + fk[t] + fb) * pw;
    __syncthreads();

    // reduce over d: 8 warps x 2 tokens
    {
        int wid = tid >> 5, lane = tid & 31;
        float pb = p_b[0];
        for (int tok = wid * 2; tok < wid * 2 + 2; tok++) {
            float s = cat_s[tok * 128 + lane] + cat_s[tok * 128 + lane + 32]
                    + cat_s[tok * 128 + lane + 64] + cat_s[tok * 128 + lane + 96];
            #pragma unroll
            for (int o = 16; o; o >>= 1) s += __shfl_xor_sync(0xFFFFFFFFu, s, o);
            if (lane == 0) p_out[bl0 + tok] = 1.f / (1.f + expf(-(s + pb)));
        }
    }
}

// ============================================================================
extern "C" void kernel_launch(void* const* d_in, const int* in_sizes, int n_in,
                              void* d_out, int out_size)
{
    const int*   q     = (const int*)  d_in[0];
    const int*   r     = (const int*)  d_in[1];
    const float* k_emb = (const float*)d_in[2];
    const float* v_emb = (const float*)d_in[3];
    const float* Mk    = (const float*)d_in[4];
    const float* Mv0   = (const float*)d_in[5];
    const float* f_W   = (const float*)d_in[6];
    const float* f_b   = (const float*)d_in[7];
    const float* p_W   = (const float*)d_in[8];
    const float* p_b   = (const float*)d_in[9];
    const float* e_W   = (const float*)d_in[10];
    const float* e_b   = (const float*)d_in[11];
    const float* a_W   = (const float*)d_in[12];
    const float* a_b   = (const float*)d_in[13];

    float* out = (float*)d_out;
    const int  P_CNT  = BB * LL;                     // 12800
    const long MV_CNT = (long)BB * 201 * MM * DD;    // 82,329,600

    float* p_out  = out;
    float* mv_out = out;
    int write_mv  = 0;
    if ((long)out_size >= (long)P_CNT + MV_CNT) {
        mv_out = out + P_CNT;
        write_mv = 1;
    }

    transpose_kernel<<<56, 256>>>(e_W, a_W, Mk, f_W);
    precompute_kernel<<<BB * LL / TOK, 256>>>(q, r, k_emb, v_emb, e_b, a_b);
    scan_kernel<<<BB * 2, 160>>>(Mv0, mv_out, write_mv);
    final_kernel<<<BB * LL / TOK2, 256>>>(f_b, p_W, p_b, p_out);
}